// round 8
// baseline (speedup 1.0000x reference)
#include <cuda_runtime.h>
#include <cuda_bf16.h>
#include <math.h>
#include <stdint.h>

#define C       128
#define NUSER   100000
#define NITEM   200000
#define NNODE   (NUSER + NITEM)
#define NEDGE   1500000
#define TM      128
#define TPB     256
#define SA      136            // smem row stride in bf16 elems (pad vs 128)
#define TILE_B  (128 * SA * 2) // bytes per bf16 tile: 34816
#define TU      ((NUSER + TM - 1) / TM)   // 782
#define TI      ((NITEM + TM - 1) / TM)   // 1563
#define MROWS   (NNODE + 128)             // padded (tiles overrun by < 128 rows)

// ---------------- scratch (device globals: allocation-free) ----------------
__device__ __nv_bfloat16 g_mh[(size_t)MROWS * C];  // mean-agg, bf16 high part
__device__ __nv_bfloat16 g_ml[(size_t)MROWS * C];  // mean-agg, bf16 low  part
__device__ int g_cnt_user[NUSER];
__device__ int g_cnt_item[NITEM];
__device__ int g_ind_user[NUSER + 1];
__device__ int g_ind_item[NITEM + 1];
__device__ int g_cur_user[NUSER];
__device__ int g_cur_item[NITEM];
__device__ int g_csr_user[NEDGE];   // sources (items) for user-destination edges
__device__ int g_csr_item[NEDGE];   // sources (users) for item-destination edges
__device__ int g_bs_user[1024];
__device__ int g_bs_item[1024];

// ---------------- warp MMA helpers ----------------
__device__ __forceinline__ uint32_t smem_u32(const void* p) {
    uint32_t a;
    asm("{ .reg .u64 t; cvta.to.shared.u64 t, %1; cvt.u32.u64 %0, t; }" : "=r"(a) : "l"(p));
    return a;
}
__device__ __forceinline__ void ldmx4(uint32_t* r, uint32_t addr) {
    asm volatile("ldmatrix.sync.aligned.m8n8.x4.shared.b16 {%0,%1,%2,%3}, [%4];"
                 : "=r"(r[0]), "=r"(r[1]), "=r"(r[2]), "=r"(r[3]) : "r"(addr));
}
__device__ __forceinline__ void mma16816(float* c, const uint32_t* a, const uint32_t* b) {
    asm volatile("mma.sync.aligned.m16n8k16.row.col.f32.bf16.bf16.f32 "
                 "{%0,%1,%2,%3},{%4,%5,%6,%7},{%8,%9},{%0,%1,%2,%3};"
                 : "+f"(c[0]), "+f"(c[1]), "+f"(c[2]), "+f"(c[3])
                 : "r"(a[0]), "r"(a[1]), "r"(a[2]), "r"(a[3]), "r"(b[0]), "r"(b[1]));
}

// One warp: rows [w*16, w*16+16) x all 128 cols. 3-term split accumulate.
// A tiles: [128][SA] bf16 (hi/lo), W tiles: [128 n][SA k] bf16 (hi/lo).
// B loaded as paired n-tiles via ldmatrix.x4 (4 mats = 2 n-tiles x 2 k-halves).
__device__ __forceinline__ void mma_gemm(uint32_t aH, uint32_t aL, uint32_t bH, uint32_t bL,
                                         int w, int l, float acc[16][4]) {
    int arow = w * 16 + (l & 7) + ((l >> 3) & 1) * 8;
    int acol = ((l >> 4) & 1) * 8;
    uint32_t aoff = (uint32_t)(arow * SA + acol) * 2;
    int mat = l >> 3, r = l & 7;
    uint32_t bpo = (uint32_t)((((mat >> 1) * 8 + r) * SA + (mat & 1) * 8) * 2);
#pragma unroll
    for (int k = 0; k < 8; k++) {
        uint32_t ah[4], al[4];
        ldmx4(ah, aH + aoff + k * 32);
        ldmx4(al, aL + aoff + k * 32);
#pragma unroll
        for (int ntp = 0; ntp < 8; ntp++) {
            uint32_t bo = bpo + (uint32_t)(ntp * 16 * SA) * 2 + k * 32;
            uint32_t bh[4], bl[4];
            ldmx4(bh, bH + bo);
            ldmx4(bl, bL + bo);
            mma16816(acc[2 * ntp],     ah, bh);
            mma16816(acc[2 * ntp],     ah, bl);
            mma16816(acc[2 * ntp],     al, bh);
            mma16816(acc[2 * ntp + 1], ah, bh + 2);
            mma16816(acc[2 * ntp + 1], ah, bl + 2);
            mma16816(acc[2 * ntp + 1], al, bh + 2);
        }
    }
}

// fp32 -> (hi, lo) bf16 split store into padded tile layout
__device__ __forceinline__ void split_store4(char* hi, char* lo, int row, int col, float4 v) {
    uint32_t off = (uint32_t)(row * SA + col) * 2;
    __nv_bfloat162 h01 = __floats2bfloat162_rn(v.x, v.y);
    __nv_bfloat162 h23 = __floats2bfloat162_rn(v.z, v.w);
    float lx = v.x - __low2float(h01);
    float ly = v.y - __high2float(h01);
    float lz = v.z - __low2float(h23);
    float lw = v.w - __high2float(h23);
    __nv_bfloat162 l01 = __floats2bfloat162_rn(lx, ly);
    __nv_bfloat162 l23 = __floats2bfloat162_rn(lz, lw);
    uint2 hp, lp;
    hp.x = *(uint32_t*)&h01; hp.y = *(uint32_t*)&h23;
    lp.x = *(uint32_t*)&l01; lp.y = *(uint32_t*)&l23;
    *(uint2*)(hi + off) = hp;
    *(uint2*)(lo + off) = lp;
}

__device__ __forceinline__ void load_weight_tile(const float* __restrict__ W,
                                                 char* hi, char* lo, int tid) {
#pragma unroll 4
    for (int idx = tid; idx < 4096; idx += TPB) {
        int row = idx >> 5, col = (idx & 31) << 2;
        float4 v = *(const float4*)(W + row * C + col);
        split_store4(hi, lo, row, col, v);
    }
}

__device__ __forceinline__ void load_act_tile(const float* __restrict__ X, size_t base, int rv,
                                              char* hi, char* lo, int tid) {
#pragma unroll 4
    for (int idx = tid; idx < 4096; idx += TPB) {
        int row = idx >> 5, col = (idx & 31) << 2;
        float4 v = (row < rv) ? *(const float4*)(X + (base + row) * (size_t)C + col)
                              : make_float4(0.f, 0.f, 0.f, 0.f);
        split_store4(hi, lo, row, col, v);
    }
}

// copy pre-split bf16 m tile (rows at mbase) into padded smem
__device__ __forceinline__ void copy_m_tile(const __nv_bfloat16* __restrict__ mh,
                                            const __nv_bfloat16* __restrict__ ml,
                                            size_t mbase, char* hi, char* lo, int tid) {
#pragma unroll 4
    for (int idx = tid; idx < 4096; idx += TPB) {
        int half = idx >> 11;          // 0: hi, 1: lo
        int e = idx & 2047;
        int row = e >> 4, i = e & 15;  // 16 chunks of 16B per 256B row
        const __nv_bfloat16* src = (half ? ml : mh) + (mbase + row) * (size_t)C + i * 8;
        char* dst = (half ? lo : hi) + (uint32_t)(row * SA + i * 8) * 2;
        *(uint4*)dst = *(const uint4*)src;
    }
}

// ---------------- CSR build (both relations per launch) ----------------
__global__ void k_zero2(int* a, int na, int* b, int nb) {
    int stride = gridDim.x * blockDim.x;
    for (int i = blockIdx.x * blockDim.x + threadIdx.x; i < na; i += stride) a[i] = 0;
    for (int i = blockIdx.x * blockDim.x + threadIdx.x; i < nb; i += stride) b[i] = 0;
}
__global__ void k_hist2(const int* __restrict__ dst_ui, int* __restrict__ cnt_i,
                        const int* __restrict__ dst_iu, int* __restrict__ cnt_u) {
    int i = blockIdx.x * blockDim.x + threadIdx.x;
    if (i < NEDGE) atomicAdd(&cnt_i[dst_ui[i]], 1);
    else if (i < 2 * NEDGE) atomicAdd(&cnt_u[dst_iu[i - NEDGE]], 1);
}
__global__ void k_scan_block2(const int* __restrict__ cnt_i, int* __restrict__ ind_i,
                              int* __restrict__ bs_i, int nbi,
                              const int* __restrict__ cnt_u, int* __restrict__ ind_u,
                              int* __restrict__ bs_u) {
    __shared__ int sm[1024];
    const int* cnt; int* indptr; int* bsums; int n; int blk;
    if ((int)blockIdx.x < nbi) { cnt = cnt_i; indptr = ind_i; bsums = bs_i; n = NITEM; blk = blockIdx.x; }
    else { cnt = cnt_u; indptr = ind_u; bsums = bs_u; n = NUSER; blk = blockIdx.x - nbi; }
    int i = blk * 1024 + threadIdx.x;
    int v = (i < n) ? cnt[i] : 0;
    sm[threadIdx.x] = v;
    __syncthreads();
#pragma unroll
    for (int off = 1; off < 1024; off <<= 1) {
        int t = (threadIdx.x >= off) ? sm[threadIdx.x - off] : 0;
        __syncthreads();
        sm[threadIdx.x] += t;
        __syncthreads();
    }
    if (i < n) indptr[i + 1] = sm[threadIdx.x];
    if (threadIdx.x == 1023) bsums[blk] = sm[1023];
}
__global__ void k_scan_bsums2(int* __restrict__ bs_i, int nbi, int* __restrict__ bs_u, int nbu) {
    __shared__ int sm[1024];
    int* bs = blockIdx.x == 0 ? bs_i : bs_u;
    int nb = blockIdx.x == 0 ? nbi : nbu;
    int v = ((int)threadIdx.x < nb) ? bs[threadIdx.x] : 0;
    sm[threadIdx.x] = v;
    __syncthreads();
#pragma unroll
    for (int off = 1; off < 1024; off <<= 1) {
        int t = (threadIdx.x >= off) ? sm[threadIdx.x - off] : 0;
        __syncthreads();
        sm[threadIdx.x] += t;
        __syncthreads();
    }
    if ((int)threadIdx.x < nb) bs[threadIdx.x] = sm[threadIdx.x] - v;  // exclusive
}
__global__ void k_scan_final2(const int* __restrict__ cnt_i, int* __restrict__ ind_i,
                              const int* __restrict__ bs_i, int* __restrict__ cur_i,
                              const int* __restrict__ cnt_u, int* __restrict__ ind_u,
                              const int* __restrict__ bs_u, int* __restrict__ cur_u) {
    int i = blockIdx.x * blockDim.x + threadIdx.x;
    if (i < NITEM) {
        int incl = ind_i[i + 1] + bs_i[i >> 10];
        ind_i[i + 1] = incl;
        cur_i[i] = incl - cnt_i[i];
        if (i == 0) ind_i[0] = 0;
    } else if (i < NNODE) {
        int j = i - NITEM;
        int incl = ind_u[j + 1] + bs_u[j >> 10];
        ind_u[j + 1] = incl;
        cur_u[j] = incl - cnt_u[j];
        if (j == 0) ind_u[0] = 0;
    }
}
__global__ void k_scatter2(const int* __restrict__ src_ui, const int* __restrict__ dst_ui,
                           int* __restrict__ cur_i, int* __restrict__ csr_i,
                           const int* __restrict__ src_iu, const int* __restrict__ dst_iu,
                           int* __restrict__ cur_u, int* __restrict__ csr_u) {
    int i = blockIdx.x * blockDim.x + threadIdx.x;
    if (i < NEDGE) {
        int p = atomicAdd(&cur_i[dst_ui[i]], 1);
        csr_i[p] = src_ui[i];
    } else if (i < 2 * NEDGE) {
        int j = i - NEDGE;
        int p = atomicAdd(&cur_u[dst_iu[j]], 1);
        csr_u[p] = src_iu[j];
    }
}

// ---------------- mean aggregation, both relations (1 warp per dst node) ----------
// writes split bf16 rows: items at [0,NITEM), users at [NITEM,NNODE)
__global__ void k_agg2(const float* __restrict__ xu, const float* __restrict__ xi,
                       const int* __restrict__ ind_i, const int* __restrict__ csr_i,
                       const int* __restrict__ ind_u, const int* __restrict__ csr_u,
                       __nv_bfloat16* __restrict__ mh, __nv_bfloat16* __restrict__ ml) {
    int a = (blockIdx.x * blockDim.x + threadIdx.x) >> 5;
    int lane = threadIdx.x & 31;
    if (a >= NNODE) return;
    const float* xs; const int *ip, *cs; int nn;
    if (a < NITEM) { xs = xu; ip = ind_i; cs = csr_i; nn = a; }
    else           { xs = xi; ip = ind_u; cs = csr_u; nn = a - NITEM; }
    int beg = ip[nn], end = ip[nn + 1];
    float4 acc = make_float4(0.f, 0.f, 0.f, 0.f);
    int j = beg;
    for (; j + 4 <= end; j += 4) {
        int s0 = cs[j], s1 = cs[j + 1], s2 = cs[j + 2], s3 = cs[j + 3];
        float4 v0 = ((const float4*)(xs + (size_t)s0 * C))[lane];
        float4 v1 = ((const float4*)(xs + (size_t)s1 * C))[lane];
        float4 v2 = ((const float4*)(xs + (size_t)s2 * C))[lane];
        float4 v3 = ((const float4*)(xs + (size_t)s3 * C))[lane];
        acc.x += v0.x + v1.x + v2.x + v3.x;
        acc.y += v0.y + v1.y + v2.y + v3.y;
        acc.z += v0.z + v1.z + v2.z + v3.z;
        acc.w += v0.w + v1.w + v2.w + v3.w;
    }
    for (; j < end; j++) {
        int s = cs[j];
        float4 v = ((const float4*)(xs + (size_t)s * C))[lane];
        acc.x += v.x; acc.y += v.y; acc.z += v.z; acc.w += v.w;
    }
    int deg = end - beg;
    float inv = 1.0f / (float)(deg > 0 ? deg : 1);
    float4 r = make_float4(acc.x * inv, acc.y * inv, acc.z * inv, acc.w * inv);
    __nv_bfloat162 h01 = __floats2bfloat162_rn(r.x, r.y);
    __nv_bfloat162 h23 = __floats2bfloat162_rn(r.z, r.w);
    float lx = r.x - __low2float(h01);
    float ly = r.y - __high2float(h01);
    float lz = r.z - __low2float(h23);
    float lw = r.w - __high2float(h23);
    __nv_bfloat162 l01 = __floats2bfloat162_rn(lx, ly);
    __nv_bfloat162 l23 = __floats2bfloat162_rn(lz, lw);
    uint2 hp, lp;
    hp.x = *(uint32_t*)&h01; hp.y = *(uint32_t*)&h23;
    lp.x = *(uint32_t*)&l01; lp.y = *(uint32_t*)&l23;
    ((uint2*)(mh + (size_t)a * C))[lane] = hp;
    ((uint2*)(ml + (size_t)a * C))[lane] = lp;
}

// ---------------- temporal encoder (mma, both types): out = x + posenc(rel)@W^T + b
#define T_WH 0
#define T_WL (TILE_B)
#define T_AH (2 * TILE_B)
#define T_AL (3 * TILE_B)
#define T_BIAS (4 * TILE_B)
#define T_REL (4 * TILE_B + 512)
#define TEMP_SMEM (4 * TILE_B + 1024)

__global__ void __launch_bounds__(TPB) k_temporal2(
    const float* __restrict__ x_user, const float* __restrict__ x_item,
    const int* __restrict__ seed,
    const int* __restrict__ t_user, const int* __restrict__ t_item,
    const int* __restrict__ b_user, const int* __restrict__ b_item,
    const float* __restrict__ Wu, const float* __restrict__ bu,
    const float* __restrict__ Wi, const float* __restrict__ bi,
    float* __restrict__ out_u, float* __restrict__ out_i)
{
    extern __shared__ char sm[];
    char* AH = sm + T_AH; char* ALo = sm + T_AL;
    float* sbias = (float*)(sm + T_BIAS);
    float* srel  = (float*)(sm + T_REL);
    uint32_t sb = smem_u32(sm);
    int tid = threadIdx.x, w = tid >> 5, l = tid & 31;

    const float* x; const int *tn, *bn; const float *W, *bias; float* out; int n, t;
    if ((int)blockIdx.x < TU) { x = x_user; tn = t_user; bn = b_user; W = Wu; bias = bu; out = out_u; n = NUSER; t = blockIdx.x; }
    else { x = x_item; tn = t_item; bn = b_item; W = Wi; bias = bi; out = out_i; n = NITEM; t = blockIdx.x - TU; }

    size_t base = (size_t)t * TM;
    int rv = min(TM, n - (int)base);

    load_weight_tile(W, sm + T_WH, sm + T_WL, tid);
    if (tid < 128) {
        sbias[tid] = bias[tid];
        int node = (int)base + tid;
        srel[tid] = (tid < rv) ? (float)(seed[bn[node]] - tn[node]) * (1.0f / 86400.0f) : 0.0f;
    }
    __syncthreads();
#pragma unroll 4
    for (int idx = tid; idx < 128 * 64; idx += TPB) {
        int r = idx >> 6, j = idx & 63;
        float div = exp2f(-0.20762050593046f * (float)j);
        float ang = srel[r] * div;
        float s, c;
        sincosf(ang, &s, &c);
        uint32_t off = (uint32_t)(r * SA + 2 * j) * 2;
        __nv_bfloat162 h = __floats2bfloat162_rn(s, c);
        float ls = s - __low2float(h), lc = c - __high2float(h);
        __nv_bfloat162 lw = __floats2bfloat162_rn(ls, lc);
        *(uint32_t*)(AH + off)  = *(uint32_t*)&h;
        *(uint32_t*)(ALo + off) = *(uint32_t*)&lw;
    }
    __syncthreads();

    float acc[16][4];
#pragma unroll
    for (int i = 0; i < 16; i++)
        acc[i][0] = acc[i][1] = acc[i][2] = acc[i][3] = 0.f;
    mma_gemm(sb + T_AH, sb + T_AL, sb + T_WH, sb + T_WL, w, l, acc);

    int qrow = l >> 2, qcol = (l & 3) * 2;
    int r0 = w * 16 + qrow, r1 = r0 + 8;
#pragma unroll
    for (int nt = 0; nt < 16; nt++) {
        int c0 = nt * 8 + qcol;
        if (r0 < rv) {
            float2 xv = *(const float2*)(x + (base + r0) * (size_t)C + c0);
            float2 o;
            o.x = acc[nt][0] + xv.x + sbias[c0];
            o.y = acc[nt][1] + xv.y + sbias[c0 + 1];
            *(float2*)(out + (base + r0) * (size_t)C + c0) = o;
        }
        if (r1 < rv) {
            float2 xv = *(const float2*)(x + (base + r1) * (size_t)C + c0);
            float2 o;
            o.x = acc[nt][2] + xv.x + sbias[c0];
            o.y = acc[nt][3] + xv.y + sbias[c0 + 1];
            *(float2*)(out + (base + r1) * (size_t)C + c0) = o;
        }
    }
}

// ---------------- SAGE layer (mma, both types): x = relu(LN(m@Wl^T + b + x@Wr^T)) --
#define S_WLH 0
#define S_WLL (TILE_B)
#define S_WRH (2 * TILE_B)
#define S_WRL (3 * TILE_B)
#define S_AH  (4 * TILE_B)
#define S_AL  (5 * TILE_B)
#define S_BIAS (6 * TILE_B)
#define S_GAM  (6 * TILE_B + 512)
#define S_BET  (6 * TILE_B + 1024)
#define SAGE_SMEM (6 * TILE_B + 1536)

__global__ void __launch_bounds__(TPB) k_sage2(
    const __nv_bfloat16* __restrict__ mh, const __nv_bfloat16* __restrict__ ml,
    float* __restrict__ xu, float* __restrict__ xi,
    const float* __restrict__ Wl_i, const float* __restrict__ b_i,
    const float* __restrict__ Wr_i, const float* __restrict__ g_i, const float* __restrict__ be_i,
    const float* __restrict__ Wl_u, const float* __restrict__ b_u,
    const float* __restrict__ Wr_u, const float* __restrict__ g_u, const float* __restrict__ be_u)
{
    extern __shared__ char sm[];
    float* sbias = (float*)(sm + S_BIAS);
    float* sgam  = (float*)(sm + S_GAM);
    float* sbet  = (float*)(sm + S_BET);
    uint32_t sb = smem_u32(sm);
    int tid = threadIdx.x, w = tid >> 5, l = tid & 31;

    float* x; const float *Wl, *bias, *Wr, *gam, *bet; int n, t; size_t mbase;
    if ((int)blockIdx.x < TI) {
        t = blockIdx.x; x = xi; Wl = Wl_i; bias = b_i; Wr = Wr_i; gam = g_i; bet = be_i;
        n = NITEM; mbase = (size_t)t * TM;
    } else {
        t = blockIdx.x - TI; x = xu; Wl = Wl_u; bias = b_u; Wr = Wr_u; gam = g_u; bet = be_u;
        n = NUSER; mbase = (size_t)NITEM + (size_t)t * TM;
    }
    size_t base = (size_t)t * TM;
    int rv = min(TM, n - (int)base);

    load_weight_tile(Wl, sm + S_WLH, sm + S_WLL, tid);
    load_weight_tile(Wr, sm + S_WRH, sm + S_WRL, tid);
    if (tid < 128) { sbias[tid] = bias[tid]; sgam[tid] = gam[tid]; sbet[tid] = bet[tid]; }
    copy_m_tile(mh, ml, mbase, sm + S_AH, sm + S_AL, tid);
    __syncthreads();

    float acc[16][4];
#pragma unroll
    for (int i = 0; i < 16; i++)
        acc[i][0] = acc[i][1] = acc[i][2] = acc[i][3] = 0.f;
    mma_gemm(sb + S_AH, sb + S_AL, sb + S_WLH, sb + S_WLL, w, l, acc);

    __syncthreads();
    load_act_tile(x, base, rv, sm + S_AH, sm + S_AL, tid);
    __syncthreads();
    mma_gemm(sb + S_AH, sb + S_AL, sb + S_WRH, sb + S_WRL, w, l, acc);

    // bias + LayerNorm + ReLU; each row owned by one lane-quad
    int qrow = l >> 2, qcol = (l & 3) * 2;
    int r0 = w * 16 + qrow, r1 = r0 + 8;
    float s1a = 0.f, s2a = 0.f, s1b = 0.f, s2b = 0.f;
#pragma unroll
    for (int nt = 0; nt < 16; nt++) {
        int c0 = nt * 8 + qcol;
        float v0 = acc[nt][0] + sbias[c0];
        float v1 = acc[nt][1] + sbias[c0 + 1];
        float v2 = acc[nt][2] + sbias[c0];
        float v3 = acc[nt][3] + sbias[c0 + 1];
        acc[nt][0] = v0; acc[nt][1] = v1; acc[nt][2] = v2; acc[nt][3] = v3;
        s1a += v0 + v1; s2a += v0 * v0 + v1 * v1;
        s1b += v2 + v3; s2b += v2 * v2 + v3 * v3;
    }
#pragma unroll
    for (int off = 1; off <= 2; off <<= 1) {
        s1a += __shfl_xor_sync(0xFFFFFFFFu, s1a, off);
        s2a += __shfl_xor_sync(0xFFFFFFFFu, s2a, off);
        s1b += __shfl_xor_sync(0xFFFFFFFFu, s1b, off);
        s2b += __shfl_xor_sync(0xFFFFFFFFu, s2b, off);
    }
    float mean0 = s1a * (1.0f / 128.0f);
    float var0  = s2a * (1.0f / 128.0f) - mean0 * mean0;
    float rstd0 = rsqrtf(var0 + 1e-5f);
    float mean1 = s1b * (1.0f / 128.0f);
    float var1  = s2b * (1.0f / 128.0f) - mean1 * mean1;
    float rstd1 = rsqrtf(var1 + 1e-5f);
#pragma unroll
    for (int nt = 0; nt < 16; nt++) {
        int c0 = nt * 8 + qcol;
        if (r0 < rv) {
            float2 o;
            o.x = fmaxf(0.f, (acc[nt][0] - mean0) * rstd0 * sgam[c0] + sbet[c0]);
            o.y = fmaxf(0.f, (acc[nt][1] - mean0) * rstd0 * sgam[c0 + 1] + sbet[c0 + 1]);
            *(float2*)(x + (base + r0) * (size_t)C + c0) = o;
        }
        if (r1 < rv) {
            float2 o;
            o.x = fmaxf(0.f, (acc[nt][2] - mean1) * rstd1 * sgam[c0] + sbet[c0]);
            o.y = fmaxf(0.f, (acc[nt][3] - mean1) * rstd1 * sgam[c0 + 1] + sbet[c0 + 1]);
            *(float2*)(x + (base + r1) * (size_t)C + c0) = o;
        }
    }
}

// ---------------- launch ----------------
extern "C" void kernel_launch(void* const* d_in, const int* in_sizes, int n_in,
                              void* d_out, int out_size) {
    const float* x_user = (const float*)d_in[0];
    const float* x_item = (const float*)d_in[1];
    const int*   seed   = (const int*)d_in[2];
    const int*   t_user = (const int*)d_in[3];
    const int*   t_item = (const int*)d_in[4];
    const int*   b_user = (const int*)d_in[5];
    const int*   b_item = (const int*)d_in[6];
    const int*   src_ui = (const int*)d_in[7];
    const int*   dst_ui = (const int*)d_in[8];
    const int*   src_iu = (const int*)d_in[9];
    const int*   dst_iu = (const int*)d_in[10];
    const float* teWu   = (const float*)d_in[11];
    const float* tebu   = (const float*)d_in[12];
    const float* teWi   = (const float*)d_in[13];
    const float* tebi   = (const float*)d_in[14];
    const float* Wl_ui  = (const float*)d_in[15];
    const float* bl_ui  = (const float*)d_in[16];
    const float* Wr_ui  = (const float*)d_in[17];
    const float* Wl_iu  = (const float*)d_in[18];
    const float* bl_iu  = (const float*)d_in[19];
    const float* Wr_iu  = (const float*)d_in[20];
    const float* g_u    = (const float*)d_in[21];
    const float* be_u   = (const float*)d_in[22];
    const float* g_i    = (const float*)d_in[23];
    const float* be_i   = (const float*)d_in[24];

    float* xu = (float*)d_out;
    float* xi = xu + (size_t)NUSER * C;

    cudaFuncSetAttribute(k_temporal2, cudaFuncAttributeMaxDynamicSharedMemorySize, TEMP_SMEM);
    cudaFuncSetAttribute(k_sage2,     cudaFuncAttributeMaxDynamicSharedMemorySize, SAGE_SMEM);

    __nv_bfloat16 *mh, *ml;
    int *cnt_u, *cnt_i, *ind_u, *ind_i, *cur_u, *cur_i, *csr_u, *csr_i, *bs_u, *bs_i;
    cudaGetSymbolAddress((void**)&mh, g_mh);
    cudaGetSymbolAddress((void**)&ml, g_ml);
    cudaGetSymbolAddress((void**)&cnt_u, g_cnt_user);
    cudaGetSymbolAddress((void**)&cnt_i, g_cnt_item);
    cudaGetSymbolAddress((void**)&ind_u, g_ind_user);
    cudaGetSymbolAddress((void**)&ind_i, g_ind_item);
    cudaGetSymbolAddress((void**)&cur_u, g_cur_user);
    cudaGetSymbolAddress((void**)&cur_i, g_cur_item);
    cudaGetSymbolAddress((void**)&csr_u, g_csr_user);
    cudaGetSymbolAddress((void**)&csr_i, g_csr_item);
    cudaGetSymbolAddress((void**)&bs_u, g_bs_user);
    cudaGetSymbolAddress((void**)&bs_i, g_bs_item);

    const int IB_U = (NUSER + 1023) / 1024;   // 98
    const int IB_I = (NITEM + 1023) / 1024;   // 196
    const int EB2 = (2 * NEDGE + 255) / 256;

    // ---- CSR build (rebuilt every call: counters are consumed) ----
    k_zero2<<<512, 256>>>(cnt_i, NITEM, cnt_u, NUSER);
    k_hist2<<<EB2, 256>>>(dst_ui, cnt_i, dst_iu, cnt_u);
    k_scan_block2<<<IB_I + IB_U, 1024>>>(cnt_i, ind_i, bs_i, IB_I, cnt_u, ind_u, bs_u);
    k_scan_bsums2<<<2, 1024>>>(bs_i, IB_I, bs_u, IB_U);
    k_scan_final2<<<(NNODE + 255) / 256, 256>>>(cnt_i, ind_i, bs_i, cur_i,
                                                cnt_u, ind_u, bs_u, cur_u);
    k_scatter2<<<EB2, 256>>>(src_ui, dst_ui, cur_i, csr_i, src_iu, dst_iu, cur_u, csr_u);

    // ---- temporal encoder (both node types, one launch) ----
    k_temporal2<<<TU + TI, TPB, TEMP_SMEM>>>(x_user, x_item, seed, t_user, t_item,
                                             b_user, b_item, teWu, tebu, teWi, tebi, xu, xi);

    // ---- 2 SAGE layers ----
    for (int l = 0; l < 2; l++) {
        size_t wo = (size_t)l * C * C;
        size_t vo = (size_t)l * C;
        k_agg2<<<(NNODE * 32 + 255) / 256, 256>>>(xu, xi, ind_i, csr_i, ind_u, csr_u, mh, ml);
        k_sage2<<<TI + TU, TPB, SAGE_SMEM>>>(mh, ml, xu, xi,
                                             Wl_ui + wo, bl_ui + vo, Wr_ui + wo, g_i + vo, be_i + vo,
                                             Wl_iu + wo, bl_iu + vo, Wr_iu + wo, g_u + vo, be_u + vo);
    }
}